// round 17
// baseline (speedup 1.0000x reference)
#include <cuda_runtime.h>
#include <cstdint>

// Problem constants
static constexpr int B = 32;
static constexpr int L = 4096;
static constexpr int C = 8;
static constexpr int T = 64;
static constexpr long long NELEM = (long long)B * L * C;   // 1,048,576

static constexpr int RED_BLOCKS  = 2048;
static constexpr int RED_THREADS = 128;
// 2048*128 threads * 4 elems = 1,048,576 == NELEM exactly

// Deterministic scratch
__device__ double   g_psum[RED_BLOCKS];
__device__ double   g_psumsq[RED_BLOCKS];
__device__ float    g_mean;
__device__ float    g_inv;    // rsqrt.approx(var + eps)
__device__ unsigned g_count = 0;   // last-block-done counter (reset after use)
// Transposed deltas: delta_t[b][c][l] = in[b,l,c] - in[b,l-1,c] (0 at l==0).
// 4 MiB, L2-resident; written coalesced by reduce, read coalesced by lif.
__device__ float    g_delta[NELEM];

__device__ __forceinline__ float rsqrt_approx(float x) {
    float r;
    asm("rsqrt.approx.f32 %0, %1;" : "=f"(r) : "f"(x));
    return r;
}

// ---------------------------------------------------------------------------
// K1: delta reduction + TRANSPOSED delta store + fused last-block finalize.
// High-occupancy shallow shape: 2048 CTAs x 128 thr x 4 elems (8192 warps,
// ~86% occ) -> BW-bound instead of latency-bound.
// Layout: idx = ((b*L)+l)*C + c, C=8. Each thread owns 4 contiguous idx
// [base, base+4) = half of one (b,l) pair (c-half = (tid&1)*4).
//   cur   = float4 @ base
//   prevC = float4 @ base-8     (same lane offsets, one l earlier)
//   d[j]  = cur[j] - prevC[j]   (= in[idx] - in[idx-C], stride C along l)
// l==0 spans idx offsets [0,8) of each batch row -> threads with
// (base & (L*C-1)) < 8 contribute all-zero (and skip the loads).
// Transposed store: d[j] -> g_delta[(b*C + chalf + j)*L + l], 4 STG.32;
// same-parity lanes hit consecutive l -> 64B-contiguous segments.
// Sum: f32 warp shuffle -> 4 double warp partials -> block partial; last
// finished block folds 2048 doubles -> g_mean/g_inv (counter reset).
// ---------------------------------------------------------------------------
__global__ void __launch_bounds__(RED_THREADS) reduce_kernel(const float* __restrict__ in) {
    const int tid  = blockIdx.x * blockDim.x + threadIdx.x;   // 0 .. 262143
    const int base = tid * 4;
    const bool head = (base & (L * C - 1)) < 8;               // l == 0 region

    float d0 = 0.f, d1 = 0.f, d2 = 0.f, d3 = 0.f;
    if (!head) {
        float4 cur   = *reinterpret_cast<const float4*>(in + base);
        float4 prevC = *reinterpret_cast<const float4*>(in + base - 8);
        d0 = cur.x - prevC.x;
        d1 = cur.y - prevC.y;
        d2 = cur.z - prevC.z;
        d3 = cur.w - prevC.w;
    }

    // Transposed store: bl = tid>>1; c-half = (tid&1)*4
    {
        const int bl    = tid >> 1;
        const int b     = bl >> 12;           // / L
        const int l     = bl & (L - 1);
        const int chalf = (tid & 1) << 2;
        float* dst = g_delta + ((long long)b * C + chalf) * L + l;
        dst[0]     = d0;
        dst[L]     = d1;
        dst[2 * L] = d2;
        dst[3 * L] = d3;
    }

    float s = (d0 + d1) + (d2 + d3);
    float q = fmaf(d0, d0, fmaf(d1, d1, fmaf(d2, d2, d3 * d3)));

    #pragma unroll
    for (int o = 16; o > 0; o >>= 1) {
        s += __shfl_down_sync(0xffffffffu, s, o);
        q += __shfl_down_sync(0xffffffffu, q, o);
    }

    __shared__ double ws[4], wq[4];
    const int t    = threadIdx.x;
    const int lane = t & 31;
    const int warp = t >> 5;     // 0..3
    if (lane == 0) { ws[warp] = (double)s; wq[warp] = (double)q; }
    __syncthreads();

    __shared__ bool isLast;
    if (warp == 0) {
        double ds = (lane < 4) ? ws[lane] : 0.0;
        double dq = (lane < 4) ? wq[lane] : 0.0;
        #pragma unroll
        for (int o = 2; o > 0; o >>= 1) {
            ds += __shfl_down_sync(0xffffffffu, ds, o);
            dq += __shfl_down_sync(0xffffffffu, dq, o);
        }
        if (lane == 0) {
            g_psum[blockIdx.x]   = ds;
            g_psumsq[blockIdx.x] = dq;
            __threadfence();
            unsigned prev = atomicAdd(&g_count, 1u);
            isLast = (prev == RED_BLOCKS - 1);
        }
    }
    __syncthreads();

    if (isLast) {
        __threadfence();   // acquire all blocks' partials
        double ds = 0.0, dq = 0.0;
        #pragma unroll
        for (int k = 0; k < 16; ++k) {
            ds += g_psum[t + k * 128];
            dq += g_psumsq[t + k * 128];
        }
        #pragma unroll
        for (int o = 16; o > 0; o >>= 1) {
            ds += __shfl_down_sync(0xffffffffu, ds, o);
            dq += __shfl_down_sync(0xffffffffu, dq, o);
        }
        __shared__ double fs[4], fq[4];
        if (lane == 0) { fs[warp] = ds; fq[warp] = dq; }
        __syncthreads();
        if (t == 0) {
            double S = (fs[0] + fs[1]) + (fs[2] + fs[3]);
            double Q = (fq[0] + fq[1]) + (fq[2] + fq[3]);
            double mean = S / (double)NELEM;
            double var  = Q / (double)NELEM - mean * mean;
            g_mean  = (float)mean;
            g_inv   = rsqrt_approx((float)var + 1e-5f);
            g_count = 0;   // reset for next graph replay
        }
    }
}

// ---------------------------------------------------------------------------
// K3: main — R16's proven lif VERBATIM (41.7us, DRAM 64%): two coalesced
// float4 delta loads from the transposed buffer, one thread = 8 l's as two
// disjoint 4-chunks (lA, lA+L/2), two independent 512B-burst float4 .cs
// stores per t, 1024 CTAs x 128 threads (balanced 6.92 CTAs/SM).
// out layout: [B, T, C, L] -> ((b*T + t)*C + c)*L + l
// ---------------------------------------------------------------------------
__global__ void __launch_bounds__(128) lif_kernel(
    const float* __restrict__ enc_w,
    const float* __restrict__ enc_b,
    const float* __restrict__ bn_gamma,
    const float* __restrict__ bn_beta,
    float* __restrict__ out)
{
    __shared__ float sw[T];
    __shared__ float sb[T];
    if (threadIdx.x < T) {
        sw[threadIdx.x] = enc_w[threadIdx.x];   // enc_w is [T,1]
        sb[threadIdx.x] = enc_b[threadIdx.x];
    }
    __syncthreads();

    const int idx = blockIdx.x * blockDim.x + threadIdx.x;  // 0 .. 131071
    const int lv  = idx & ((L / 8) - 1);        // 0..511
    const int c   = (idx >> 9) & (C - 1);
    const int b   = idx >> 12;
    const int lA  = lv * 4;                     // chunk A: [lA, lA+4)

    const float mean = g_mean;
    const float inv  = g_inv;
    const float ga   = bn_gamma[0];
    const float be   = bn_beta[0];

    // Coalesced transposed-delta loads (delta_t[b][c][l], 0 already at l==0)
    const float* drow = g_delta + ((long long)b * C + c) * L;
    float4 rA = *reinterpret_cast<const float4*>(drow + lA);
    float4 rB = *reinterpret_cast<const float4*>(drow + lA + (L / 2));

    float dA[4], dB[4];
    {
        const float* pa = &rA.x;
        const float* pb = &rB.x;
        #pragma unroll
        for (int j = 0; j < 4; ++j) {
            float xa = (pa[j] - mean) * inv;
            dA[j] = xa * ga + be;
            float xb = (pb[j] - mean) * inv;
            dB[j] = xb * ga + be;
        }
    }

    float vA0 = 0.f, vA1 = 0.f, vA2 = 0.f, vA3 = 0.f;
    float vB0 = 0.f, vB1 = 0.f, vB2 = 0.f, vB3 = 0.f;

    float* opA = out + (((long long)b * T) * C + c) * L + lA;
    float* opB = opA + (L / 2);

    #pragma unroll 8
    for (int t = 0; t < T; ++t) {
        const float w  = sw[t];
        const float bb = sb[t];
        const long long off = (long long)t * (C * L);
        float4 sa, sbv;

        float x;
        x = fmaf(dA[0], w, bb); vA0 = vA0 + (x - vA0) * 0.5f;
        bool p0 = (vA0 >= 1.0f); sa.x = p0 ? 1.0f : 0.0f; vA0 = p0 ? 0.0f : vA0;
        x = fmaf(dA[1], w, bb); vA1 = vA1 + (x - vA1) * 0.5f;
        bool p1 = (vA1 >= 1.0f); sa.y = p1 ? 1.0f : 0.0f; vA1 = p1 ? 0.0f : vA1;
        x = fmaf(dA[2], w, bb); vA2 = vA2 + (x - vA2) * 0.5f;
        bool p2 = (vA2 >= 1.0f); sa.z = p2 ? 1.0f : 0.0f; vA2 = p2 ? 0.0f : vA2;
        x = fmaf(dA[3], w, bb); vA3 = vA3 + (x - vA3) * 0.5f;
        bool p3 = (vA3 >= 1.0f); sa.w = p3 ? 1.0f : 0.0f; vA3 = p3 ? 0.0f : vA3;

        x = fmaf(dB[0], w, bb); vB0 = vB0 + (x - vB0) * 0.5f;
        bool q0 = (vB0 >= 1.0f); sbv.x = q0 ? 1.0f : 0.0f; vB0 = q0 ? 0.0f : vB0;
        x = fmaf(dB[1], w, bb); vB1 = vB1 + (x - vB1) * 0.5f;
        bool q1 = (vB1 >= 1.0f); sbv.y = q1 ? 1.0f : 0.0f; vB1 = q1 ? 0.0f : vB1;
        x = fmaf(dB[2], w, bb); vB2 = vB2 + (x - vB2) * 0.5f;
        bool q2 = (vB2 >= 1.0f); sbv.z = q2 ? 1.0f : 0.0f; vB2 = q2 ? 0.0f : vB2;
        x = fmaf(dB[3], w, bb); vB3 = vB3 + (x - vB3) * 0.5f;
        bool q3 = (vB3 >= 1.0f); sbv.w = q3 ? 1.0f : 0.0f; vB3 = q3 ? 0.0f : vB3;

        __stcs(reinterpret_cast<float4*>(opA + off), sa);
        __stcs(reinterpret_cast<float4*>(opB + off), sbv);
    }
}

// ---------------------------------------------------------------------------
extern "C" void kernel_launch(void* const* d_in, const int* in_sizes, int n_in,
                              void* d_out, int out_size)
{
    const float* in       = (const float*)d_in[0];
    const float* bn_gamma = (const float*)d_in[1];
    const float* bn_beta  = (const float*)d_in[2];
    const float* enc_w    = (const float*)d_in[3];
    const float* enc_b    = (const float*)d_in[4];
    float* out            = (float*)d_out;

    reduce_kernel<<<RED_BLOCKS, RED_THREADS>>>(in);

    const int total_thr = B * C * (L / 8);      // 131072
    lif_kernel<<<total_thr / 128, 128>>>(enc_w, enc_b, bn_gamma, bn_beta, out);
}